// round 15
// baseline (speedup 1.0000x reference)
#include <cuda_runtime.h>
#include <cuda_fp16.h>
#include <math.h>
#include <stdint.h>

// ---------------------------------------------------------------------------
// Problem constants
// ---------------------------------------------------------------------------
#define BWIN    2048
#define N_TOK   49
#define C_DIM   512
#define N_HEADS 16
#define HD      32
#define QKV_N   1536
#define M_ROWS  (BWIN * N_TOK)     // 100352 = 784 * 128
#define NN      (N_TOK * N_TOK)    // 2401
#define NWMASK  64

// ---------------------------------------------------------------------------
// Scratch (static device globals)
// ---------------------------------------------------------------------------
__device__ float g_qkv[(size_t)M_ROWS * QKV_N];      // fp32 qkv
__device__ __half g_xh[(size_t)M_ROWS * C_DIM];      // x split hi   [M,K]
__device__ __half g_xl[(size_t)M_ROWS * C_DIM];      // x split lo
__device__ __half g_aoh[(size_t)M_ROWS * C_DIM];     // attn out hi (1-term path)
__device__ __half g_qwh[C_DIM * QKV_N];              // qkv_w hi  [K,N]
__device__ __half g_qwl[C_DIM * QKV_N];              // qkv_w lo
__device__ __half g_pwh[C_DIM * C_DIM];              // proj_w hi [K,N]
__device__ float g_pb [N_HEADS * NN];
__device__ float g_qkvbias[QKV_N];

// ---------------------------------------------------------------------------
// Helpers
// ---------------------------------------------------------------------------
__device__ __forceinline__ uint32_t pack2(__half a, __half b) {
    __half2 v = __halves2half2(a, b);
    return *(uint32_t*)&v;
}
__device__ __forceinline__ void split1(float v, __half& h, __half& l) {
    h = __float2half_rn(v);
    l = __float2half_rn(v - __half2float(h));
}

__device__ __forceinline__ void mma_f16(float d[4],
                                        const uint32_t a[4],
                                        const uint32_t b[2]) {
    asm volatile(
        "mma.sync.aligned.m16n8k16.row.col.f32.f16.f16.f32 "
        "{%0,%1,%2,%3}, {%4,%5,%6,%7}, {%8,%9}, {%0,%1,%2,%3};\n"
        : "+f"(d[0]), "+f"(d[1]), "+f"(d[2]), "+f"(d[3])
        : "r"(a[0]), "r"(a[1]), "r"(a[2]), "r"(a[3]), "r"(b[0]), "r"(b[1]));
}
__device__ __forceinline__ void ldsm_x4(uint32_t r[4], uint32_t addr) {
    asm volatile("ldmatrix.sync.aligned.m8n8.x4.shared.b16 {%0,%1,%2,%3}, [%4];\n"
                 : "=r"(r[0]), "=r"(r[1]), "=r"(r[2]), "=r"(r[3]) : "r"(addr));
}
__device__ __forceinline__ void ldsm_x2t(uint32_t r[2], uint32_t addr) {
    asm volatile("ldmatrix.sync.aligned.m8n8.x2.trans.shared.b16 {%0,%1}, [%2];\n"
                 : "=r"(r[0]), "=r"(r[1]) : "r"(addr));
}
__device__ __forceinline__ void cp16(uint32_t dst, const void* src) {
    asm volatile("cp.async.cg.shared.global [%0], [%1], 16;\n" :: "r"(dst), "l"(src));
}
__device__ __forceinline__ void cp_commit() { asm volatile("cp.async.commit_group;\n"); }
__device__ __forceinline__ void cp_wait1()  { asm volatile("cp.async.wait_group 1;\n" ::: "memory"); }

// ---------------------------------------------------------------------------
// Split kernels: fp32 -> fp16 hi/lo and hi-only
// ---------------------------------------------------------------------------
__global__ void split_kernel(const float* __restrict__ src,
                             __half* __restrict__ dh,
                             __half* __restrict__ dl, int n4) {
    int i = blockIdx.x * blockDim.x + threadIdx.x;
    if (i >= n4) return;
    float4 v = ((const float4*)src)[i];
    __half hx, lx, hy, ly, hz, lz, hw, lw;
    split1(v.x, hx, lx); split1(v.y, hy, ly);
    split1(v.z, hz, lz); split1(v.w, hw, lw);
    uint2 ph, pl;
    ph.x = pack2(hx, hy); ph.y = pack2(hz, hw);
    pl.x = pack2(lx, ly); pl.y = pack2(lz, lw);
    ((uint2*)dh)[i] = ph;
    ((uint2*)dl)[i] = pl;
}

__global__ void split_hi_kernel(const float* __restrict__ src,
                                __half* __restrict__ dh, int n4) {
    int i = blockIdx.x * blockDim.x + threadIdx.x;
    if (i >= n4) return;
    float4 v = ((const float4*)src)[i];
    uint2 ph;
    ph.x = pack2(__float2half_rn(v.x), __float2half_rn(v.y));
    ph.y = pack2(__float2half_rn(v.z), __float2half_rn(v.w));
    ((uint2*)dh)[i] = ph;
}

// ---------------------------------------------------------------------------
// Kernel 1: RPE table MLP + bias gather + qkv bias vector
// ---------------------------------------------------------------------------
__device__ __forceinline__ float coord_feat(int x) {
    float xs = (float)x * (8.0f / 121.0f);
    float v = log1pf(fabsf(xs)) * 0.48089834696298783f; // 1/ln(8)
    return copysignf(v, xs);
}

__global__ void setup_kernel(const float* __restrict__ rpe_w1,
                             const float* __restrict__ rpe_b1,
                             const float* __restrict__ rpe_w2,
                             const float* __restrict__ q_bias,
                             const float* __restrict__ v_bias) {
    __shared__ float sbt[169 * N_HEADS];
    const int tid = threadIdx.x; // 256 threads

    if (tid < 169) {
        int a = tid / 13, b = tid % 13;
        float c0 = coord_feat(b - 6);
        float c1 = coord_feat(a - 6);
        float acc[N_HEADS];
        #pragma unroll
        for (int t = 0; t < N_HEADS; t++) acc[t] = 0.f;
        for (int j = 0; j < 512; j++) {
            float h1 = fmaf(c0, rpe_w1[j], fmaf(c1, rpe_w1[512 + j], rpe_b1[j]));
            h1 = fmaxf(h1, 0.f);
            const float* w2 = rpe_w2 + j * N_HEADS;
            #pragma unroll
            for (int t = 0; t < N_HEADS; t++) acc[t] = fmaf(h1, w2[t], acc[t]);
        }
        #pragma unroll
        for (int t = 0; t < N_HEADS; t++) sbt[tid * N_HEADS + t] = acc[t];
    }

    for (int c = tid; c < QKV_N; c += 256) {
        float v = 0.f;
        if (c < 512)        v = q_bias[c];
        else if (c >= 1024) v = v_bias[c - 1024];
        g_qkvbias[c] = v;
    }
    __syncthreads();

    for (int idx = tid; idx < N_HEADS * NN; idx += 256) {
        int h   = idx / NN;
        int rem = idx % NN;
        int n = rem / N_TOK, m = rem % N_TOK;
        int di = (n / 7) - (m / 7);
        int dj = (n % 7) - (m % 7);
        int r = (dj + 6) * 13 + (di + 6);
        float bt = sbt[r * N_HEADS + h];
        g_pb[idx] = 16.f / (1.f + expf(-bt));
    }
}

// ---------------------------------------------------------------------------
// Pipelined split-fp16 tensor-core GEMM, v4: 256 threads = 8 warps,
// warp tile 64x32 (2x4 warp grid), 2-stage cp.async ring, 2 CTAs/SM
// => 16 warps/SM (issue-limit experiment). `vstart` as before.
// ---------------------------------------------------------------------------
#define SA_STR 40
#define SB_STR 136
#define ASIZE (128 * SA_STR)
#define BSIZE (32 * SB_STR)
#define SMEM_BYTES ((2 * (2 * ASIZE + 2 * BSIZE)) * 2)  // 75776 B

__device__ __forceinline__ void gemm_issue(
    int it, int buf, int iters, int tid, int terms,
    const __half* Ah, const __half* Al,
    const __half* Bh, const __half* Bl,
    size_t Abase, int nblk, int N, int K,
    uint32_t sAh32, uint32_t sAl32, uint32_t sBh32, uint32_t sBl32)
{
    if (it < iters) {
        const int k0 = it * 32;
        const uint32_t aoff = (uint32_t)buf * (ASIZE * 2);
        const uint32_t boff = (uint32_t)buf * (BSIZE * 2);
        #pragma unroll
        for (int p = 0; p < 2; p++) {
            int c = tid + p * 256;
            int row = c >> 2, seg = (c & 3) * 8;
            size_t go = Abase + (size_t)row * K + k0 + seg;
            uint32_t ds = (uint32_t)(row * SA_STR + seg) * 2;
            cp16(sAh32 + aoff + ds, Ah + go);
            if (terms == 3) cp16(sAl32 + aoff + ds, Al + go);
        }
        #pragma unroll
        for (int p = 0; p < 2; p++) {
            int c = tid + p * 256;
            int row = c >> 4, seg = (c & 15) * 8;
            size_t go = (size_t)(k0 + row) * N + nblk + seg;
            uint32_t ds = (uint32_t)(row * SB_STR + seg) * 2;
            cp16(sBh32 + boff + ds, Bh + go);
            if (terms == 3) cp16(sBl32 + boff + ds, Bl + go);
        }
    }
    cp_commit();
}

__device__ __forceinline__ void gemm_core(
    const __half* __restrict__ Ah, const __half* __restrict__ Al,
    const __half* __restrict__ Bh, const __half* __restrict__ Bl,
    const float* __restrict__ bias, float* __restrict__ C, int N, int K,
    int vstart)
{
    extern __shared__ __half smem[];
    __half* sAh = smem;
    __half* sAl = sAh + 2 * ASIZE;
    __half* sBh = sAl + 2 * ASIZE;
    __half* sBl = sBh + 2 * BSIZE;

    const int tid  = threadIdx.x;          // 256 threads
    const int bm   = blockIdx.y, bn = blockIdx.x;
    const int terms = (bn < vstart) ? 3 : 1;
    const int lane = tid & 31;
    const int w    = tid >> 5;              // 0..7
    const int wm   = (w >> 2) * 64;         // 0 or 64
    const int wn   = (w & 3) * 32;          // 0,32,64,96
    const int l15  = lane & 15;
    const int lhi8 = (lane >> 4) * 8;

    const size_t Abase = (size_t)bm * 128 * K;
    const int nblk = bn * 128;

    const uint32_t sAh32 = (uint32_t)__cvta_generic_to_shared(sAh);
    const uint32_t sAl32 = (uint32_t)__cvta_generic_to_shared(sAl);
    const uint32_t sBh32 = (uint32_t)__cvta_generic_to_shared(sBh);
    const uint32_t sBl32 = (uint32_t)__cvta_generic_to_shared(sBl);

    float acc[4][4][4];
    #pragma unroll
    for (int mi = 0; mi < 4; mi++)
        #pragma unroll
        for (int ni = 0; ni < 4; ni++)
            #pragma unroll
            for (int r = 0; r < 4; r++) acc[mi][ni][r] = 0.f;

    const int iters = K / 32;
    gemm_issue(0, 0, iters, tid, terms, Ah, Al, Bh, Bl, Abase, nblk, N, K,
               sAh32, sAl32, sBh32, sBl32);
    gemm_issue(1, 1, iters, tid, terms, Ah, Al, Bh, Bl, Abase, nblk, N, K,
               sAh32, sAl32, sBh32, sBl32);

    for (int it = 0; it < iters; it++) {
        const int buf = it & 1;
        cp_wait1();
        __syncthreads();

        const uint32_t aoff = (uint32_t)buf * (ASIZE * 2);
        const uint32_t boff = (uint32_t)buf * (BSIZE * 2);

        if (terms == 3) {
            #pragma unroll
            for (int ks = 0; ks < 32; ks += 16) {
                uint32_t bh[4][2], bl[4][2];
                #pragma unroll
                for (int ni = 0; ni < 4; ni++) {
                    uint32_t ds = (uint32_t)((ks + l15) * SB_STR + wn + ni * 8) * 2;
                    ldsm_x2t(bh[ni], sBh32 + boff + ds);
                    ldsm_x2t(bl[ni], sBl32 + boff + ds);
                }
                #pragma unroll
                for (int mi = 0; mi < 4; mi++) {
                    uint32_t ds = (uint32_t)((wm + mi * 16 + l15) * SA_STR + ks + lhi8) * 2;
                    uint32_t ah[4], al[4];
                    ldsm_x4(ah, sAh32 + aoff + ds);
                    ldsm_x4(al, sAl32 + aoff + ds);
                    #pragma unroll
                    for (int ni = 0; ni < 4; ni++) {
                        mma_f16(acc[mi][ni], ah, bh[ni]);
                        mma_f16(acc[mi][ni], ah, bl[ni]);
                        mma_f16(acc[mi][ni], al, bh[ni]);
                    }
                }
            }
        } else {
            #pragma unroll
            for (int ks = 0; ks < 32; ks += 16) {
                uint32_t bh[4][2];
                #pragma unroll
                for (int ni = 0; ni < 4; ni++) {
                    uint32_t ds = (uint32_t)((ks + l15) * SB_STR + wn + ni * 8) * 2;
                    ldsm_x2t(bh[ni], sBh32 + boff + ds);
                }
                #pragma unroll
                for (int mi = 0; mi < 4; mi++) {
                    uint32_t ds = (uint32_t)((wm + mi * 16 + l15) * SA_STR + ks + lhi8) * 2;
                    uint32_t ah[4];
                    ldsm_x4(ah, sAh32 + aoff + ds);
                    #pragma unroll
                    for (int ni = 0; ni < 4; ni++)
                        mma_f16(acc[mi][ni], ah, bh[ni]);
                }
            }
        }
        __syncthreads();
        gemm_issue(it + 2, buf, iters, tid, terms, Ah, Al, Bh, Bl, Abase, nblk, N, K,
                   sAh32, sAl32, sBh32, sBl32);
    }

    const int g  = lane >> 2;
    const int t2 = (lane & 3) * 2;
    #pragma unroll
    for (int mi = 0; mi < 4; mi++) {
        int row = bm * 128 + wm + mi * 16 + g;
        #pragma unroll
        for (int ni = 0; ni < 4; ni++) {
            int col = bn * 128 + wn + ni * 8 + t2;
            float b0 = bias[col], b1 = bias[col + 1];
            float2 o0 = make_float2(acc[mi][ni][0] + b0, acc[mi][ni][1] + b1);
            float2 o1 = make_float2(acc[mi][ni][2] + b0, acc[mi][ni][3] + b1);
            *(float2*)(C + (size_t)row * N + col)       = o0;
            *(float2*)(C + (size_t)(row + 8) * N + col) = o1;
        }
    }
}

__global__ void __launch_bounds__(256, 2)
qkv_gemm_kernel() {
    // N-tiles 0..7 are q,k (3-term); tiles 8..11 are v (1-term fp16)
    gemm_core(g_xh, g_xl, g_qwh, g_qwl, g_qkvbias, g_qkv, QKV_N, C_DIM, 8);
}

__global__ void __launch_bounds__(256, 2)
proj_gemm_kernel(const float* __restrict__ proj_b, float* __restrict__ out) {
    // final projection: 1-term fp16 (lo operands never read)
    gemm_core(g_aoh, g_aoh, g_pwh, g_pwh, proj_b, out, C_DIM, C_DIM, 0);
}

// ---------------------------------------------------------------------------
// Kernel 3: tensor-core attention per (window, head).
// QK^T: 3-term split fp16 (sensitive path). PV: 1-term fp16 (linear path).
// Output: hi-only fp16 (proj is 1-term).
// ---------------------------------------------------------------------------
#define ATT_QH  0
#define ATT_QL  5120
#define ATT_KTH 10240
#define ATT_KTL 14848
#define ATT_VH  19456
#define ATT_SS  29696
#define ATT_TOT (29696 + 64 * 66 * 4)   // 46592 B
#define ATT_PH  0                        // P hi overlays dead Q region

__global__ void __launch_bounds__(256, 2)
attn_kernel(const float* __restrict__ mask, const float* __restrict__ logit_scale) {
    const int b = blockIdx.x >> 4;
    const int h = blockIdx.x & 15;
    const int tid  = threadIdx.x;
    const int lane = tid & 31;
    const int w    = tid >> 5;

    __shared__ __align__(16) char sm[ATT_TOT];
    __half* sQh  = (__half*)(sm + ATT_QH);
    __half* sQl  = (__half*)(sm + ATT_QL);
    __half* sKth = (__half*)(sm + ATT_KTH);
    __half* sKtl = (__half*)(sm + ATT_KTL);
    __half* sVh  = (__half*)(sm + ATT_VH);
    __half* sPh  = (__half*)(sm + ATT_PH);
    float* sS = (float*)(sm + ATT_SS);
    const uint32_t smb = (uint32_t)__cvta_generic_to_shared(sm);

    // ---- Phase 1: stage q,k fp32; V hi-only fp16 ----
    const float* base = g_qkv + (size_t)b * N_TOK * QKV_N + h * HD;
    #pragma unroll
    for (int p = 0; p < 8; p++) {
        int idx = tid + p * 256;
        int r = idx >> 5, d = idx & 31;
        float qv = 0.f, kv = 0.f, vv = 0.f;
        if (r < N_TOK) {
            const float* pp = base + (size_t)r * QKV_N + d;
            qv = pp[0]; kv = pp[512]; vv = pp[1024];
        }
        sS[r * 66 + d]      = qv;
        sS[r * 66 + 32 + d] = kv;
        sVh[r * 40 + d] = __float2half_rn(vv);
    }
    __syncthreads();

    // ---- Phase 2: normalize rows (uniform), split Q / K^T ----
    {
        const int r  = tid >> 2;
        const int qd = (tid & 3) * 8;
        float qv[8], kv[8];
        float sq = 0.f, sk = 0.f;
        #pragma unroll
        for (int j = 0; j < 8; j++) {
            qv[j] = sS[r * 66 + qd + j];
            kv[j] = sS[r * 66 + 32 + qd + j];
            sq = fmaf(qv[j], qv[j], sq);
            sk = fmaf(kv[j], kv[j], sk);
        }
        sq += __shfl_xor_sync(0xffffffff, sq, 1);
        sq += __shfl_xor_sync(0xffffffff, sq, 2);
        sk += __shfl_xor_sync(0xffffffff, sk, 1);
        sk += __shfl_xor_sync(0xffffffff, sk, 2);
        float hs  = __expf(fminf(logit_scale[h], 4.605170185988091f));
        float qsc = rsqrtf(fmaxf(sq, 1e-12f)) * hs;
        float ksc = rsqrtf(fmaxf(sk, 1e-12f));
        #pragma unroll
        for (int j = 0; j < 8; j += 2) {
            __half h0, l0, h1, l1;
            split1(qv[j] * qsc, h0, l0);
            split1(qv[j + 1] * qsc, h1, l1);
            *(uint32_t*)&sQh[r * 40 + qd + j] = pack2(h0, h1);
            *(uint32_t*)&sQl[r * 40 + qd + j] = pack2(l0, l1);
        }
        #pragma unroll
        for (int j = 0; j < 8; j++) {
            __half kh, kl;
            split1(kv[j] * ksc, kh, kl);
            sKth[(qd + j) * 72 + r] = kh;
            sKtl[(qd + j) * 72 + r] = kl;
        }
    }
    __syncthreads();

    // ---- Phase 3: S = Qn @ Kn^T (3-term) ----
    {
        const int m0  = (w & 3) * 16;
        const int n0  = (w >> 2) * 32;
        const int l15 = lane & 15;
        const int lhi8 = (lane >> 4) * 8;
        float acc[4][4];
        #pragma unroll
        for (int ni = 0; ni < 4; ni++)
            #pragma unroll
            for (int r = 0; r < 4; r++) acc[ni][r] = 0.f;

        #pragma unroll
        for (int ks = 0; ks < 32; ks += 16) {
            uint32_t ah[4], al[4];
            uint32_t dsA = (uint32_t)(ATT_QH) + (uint32_t)((m0 + l15) * 40 + ks + lhi8) * 2;
            ldsm_x4(ah, smb + dsA);
            ldsm_x4(al, smb + dsA + (ATT_QL - ATT_QH));
            #pragma unroll
            for (int ni = 0; ni < 4; ni++) {
                uint32_t bh[2], bl[2];
                uint32_t dsB = (uint32_t)(ATT_KTH) + (uint32_t)((ks + l15) * 72 + n0 + ni * 8) * 2;
                ldsm_x2t(bh, smb + dsB);
                ldsm_x2t(bl, smb + dsB + (ATT_KTL - ATT_KTH));
                mma_f16(acc[ni], ah, bh);
                mma_f16(acc[ni], ah, bl);
                mma_f16(acc[ni], al, bh);
            }
        }
        const int g  = lane >> 2;
        const int t2 = (lane & 3) * 2;
        #pragma unroll
        for (int ni = 0; ni < 4; ni++) {
            int c = n0 + ni * 8 + t2;
            *(float2*)&sS[(m0 + g) * 66 + c]     = make_float2(acc[ni][0], acc[ni][1]);
            *(float2*)&sS[(m0 + 8 + g) * 66 + c] = make_float2(acc[ni][2], acc[ni][3]);
        }
    }
    __syncthreads();

    // ---- Phase 4: softmax (uniform); P hi-only fp16 ----
    {
        const int r  = tid >> 2;
        const int c0 = (tid & 3) * 16;
        const int rr = (r < N_TOK) ? r : 0;
        const int ww = b & (NWMASK - 1);
        const float* pbr = g_pb + h * NN + rr * N_TOK;
        const float* mr  = mask + (size_t)ww * NN + rr * N_TOK;
        float vals[16];
        float mx = -1e30f;
        #pragma unroll
        for (int i = 0; i < 16; i++) {
            int m = c0 + i;
            float v = -1e30f;
            if (m < N_TOK) v = sS[r * 66 + m] + pbr[m] + mr[m];
            vals[i] = v;
            mx = fmaxf(mx, v);
        }
        mx = fmaxf(mx, __shfl_xor_sync(0xffffffff, mx, 1));
        mx = fmaxf(mx, __shfl_xor_sync(0xffffffff, mx, 2));
        float sum = 0.f;
        #pragma unroll
        for (int i = 0; i < 16; i++) {
            float e = (c0 + i < N_TOK) ? __expf(vals[i] - mx) : 0.f;
            vals[i] = e;
            sum += e;
        }
        sum += __shfl_xor_sync(0xffffffff, sum, 1);
        sum += __shfl_xor_sync(0xffffffff, sum, 2);
        float inv = 1.f / sum;
        #pragma unroll
        for (int i = 0; i < 16; i += 2) {
            *(uint32_t*)&sPh[r * 72 + c0 + i] =
                pack2(__float2half_rn(vals[i] * inv), __float2half_rn(vals[i + 1] * inv));
        }
    }
    __syncthreads();

    // ---- Phase 5: O = P @ V (1-term); hi-only output ----
    {
        const int m0  = (w & 3) * 16;
        const int n0  = (w >> 2) * 16;
        const int l15 = lane & 15;
        const int lhi8 = (lane >> 4) * 8;
        float acc[2][4];
        #pragma unroll
        for (int ni = 0; ni < 2; ni++)
            #pragma unroll
            for (int r = 0; r < 4; r++) acc[ni][r] = 0.f;

        #pragma unroll
        for (int ks = 0; ks < 64; ks += 16) {
            uint32_t ah[4];
            uint32_t dsA = (uint32_t)(ATT_PH) + (uint32_t)((m0 + l15) * 72 + ks + lhi8) * 2;
            ldsm_x4(ah, smb + dsA);
            #pragma unroll
            for (int ni = 0; ni < 2; ni++) {
                uint32_t bh[2];
                uint32_t dsB = (uint32_t)(ATT_VH) + (uint32_t)((ks + l15) * 40 + n0 + ni * 8) * 2;
                ldsm_x2t(bh, smb + dsB);
                mma_f16(acc[ni], ah, bh);
            }
        }
        const int g  = lane >> 2;
        const int t2 = (lane & 3) * 2;
        #pragma unroll
        for (int ni = 0; ni < 2; ni++) {
            int col  = h * HD + n0 + ni * 8 + t2;
            int row0 = m0 + g, row1 = m0 + 8 + g;
            if (row0 < N_TOK) {
                size_t o = ((size_t)b * N_TOK + row0) * C_DIM + col;
                *(uint32_t*)(g_aoh + o) =
                    pack2(__float2half_rn(acc[ni][0]), __float2half_rn(acc[ni][1]));
            }
            if (row1 < N_TOK) {
                size_t o = ((size_t)b * N_TOK + row1) * C_DIM + col;
                *(uint32_t*)(g_aoh + o) =
                    pack2(__float2half_rn(acc[ni][2]), __float2half_rn(acc[ni][3]));
            }
        }
    }
}

// ---------------------------------------------------------------------------
// Launch
// ---------------------------------------------------------------------------
extern "C" void kernel_launch(void* const* d_in, const int* in_sizes, int n_in,
                              void* d_out, int out_size) {
    const float* x           = (const float*)d_in[0];
    const float* mask        = (const float*)d_in[1];
    const float* qkv_w       = (const float*)d_in[2];
    const float* q_bias      = (const float*)d_in[3];
    const float* v_bias      = (const float*)d_in[4];
    const float* logit_scale = (const float*)d_in[5];
    const float* rpe_w1      = (const float*)d_in[6];
    const float* rpe_b1      = (const float*)d_in[7];
    const float* rpe_w2      = (const float*)d_in[8];
    const float* proj_w      = (const float*)d_in[9];
    const float* proj_b      = (const float*)d_in[10];
    float* out = (float*)d_out;

    cudaFuncSetAttribute(qkv_gemm_kernel,
                         cudaFuncAttributeMaxDynamicSharedMemorySize, SMEM_BYTES);
    cudaFuncSetAttribute(proj_gemm_kernel,
                         cudaFuncAttributeMaxDynamicSharedMemorySize, SMEM_BYTES);

    __half *xh, *xl, *qwh, *qwl, *pwh;
    cudaGetSymbolAddress((void**)&xh,  g_xh);
    cudaGetSymbolAddress((void**)&xl,  g_xl);
    cudaGetSymbolAddress((void**)&qwh, g_qwh);
    cudaGetSymbolAddress((void**)&qwl, g_qwl);
    cudaGetSymbolAddress((void**)&pwh, g_pwh);

    setup_kernel<<<1, 256>>>(rpe_w1, rpe_b1, rpe_w2, q_bias, v_bias);

    {
        int n4 = M_ROWS * C_DIM / 4;
        split_kernel<<<(n4 + 255) / 256, 256>>>(x, xh, xl, n4);
    }
    {
        int n4 = C_DIM * QKV_N / 4;
        split_kernel<<<(n4 + 255) / 256, 256>>>(qkv_w, qwh, qwl, n4);
    }
    {
        int n4 = C_DIM * C_DIM / 4;
        split_hi_kernel<<<(n4 + 255) / 256, 256>>>(proj_w, pwh, n4);
    }

    // QKV: [100352,512] @ [512,1536]
    qkv_gemm_kernel<<<dim3(QKV_N / 128, M_ROWS / 128), 256, SMEM_BYTES>>>();

    attn_kernel<<<BWIN * N_HEADS, 256>>>(mask, logit_scale);

    // proj: [100352,512] @ [512,512] -> d_out
    proj_gemm_kernel<<<dim3(C_DIM / 128, M_ROWS / 128), 256, SMEM_BYTES>>>(proj_b, out);
}

// round 16
// speedup vs baseline: 1.0580x; 1.0580x over previous
#include <cuda_runtime.h>
#include <cuda_fp16.h>
#include <math.h>
#include <stdint.h>

// ---------------------------------------------------------------------------
// Problem constants
// ---------------------------------------------------------------------------
#define BWIN    2048
#define N_TOK   49
#define C_DIM   512
#define N_HEADS 16
#define HD      32
#define QKV_N   1536
#define M_ROWS  (BWIN * N_TOK)     // 100352 = 784 * 128
#define NN      (N_TOK * N_TOK)    // 2401
#define NWMASK  64

// ---------------------------------------------------------------------------
// Scratch (static device globals)
// ---------------------------------------------------------------------------
__device__ float g_qkv[(size_t)M_ROWS * QKV_N];      // fp32 qkv
__device__ __half g_xh[(size_t)M_ROWS * C_DIM];      // x split hi   [M,K]
__device__ __half g_xl[(size_t)M_ROWS * C_DIM];      // x split lo
__device__ __half g_aoh[(size_t)M_ROWS * C_DIM];     // attn out hi (1-term path)
__device__ __half g_qwh[C_DIM * QKV_N];              // qkv_w hi  [K,N]
__device__ __half g_qwl[C_DIM * QKV_N];              // qkv_w lo
__device__ __half g_pwh[C_DIM * C_DIM];              // proj_w hi [K,N]
__device__ float g_pb [N_HEADS * NN];
__device__ float g_qkvbias[QKV_N];

// ---------------------------------------------------------------------------
// Helpers
// ---------------------------------------------------------------------------
__device__ __forceinline__ uint32_t pack2(__half a, __half b) {
    __half2 v = __halves2half2(a, b);
    return *(uint32_t*)&v;
}
__device__ __forceinline__ void split1(float v, __half& h, __half& l) {
    h = __float2half_rn(v);
    l = __float2half_rn(v - __half2float(h));
}

__device__ __forceinline__ void mma_f16(float d[4],
                                        const uint32_t a[4],
                                        const uint32_t b[2]) {
    asm volatile(
        "mma.sync.aligned.m16n8k16.row.col.f32.f16.f16.f32 "
        "{%0,%1,%2,%3}, {%4,%5,%6,%7}, {%8,%9}, {%0,%1,%2,%3};\n"
        : "+f"(d[0]), "+f"(d[1]), "+f"(d[2]), "+f"(d[3])
        : "r"(a[0]), "r"(a[1]), "r"(a[2]), "r"(a[3]), "r"(b[0]), "r"(b[1]));
}
__device__ __forceinline__ void ldsm_x4(uint32_t r[4], uint32_t addr) {
    asm volatile("ldmatrix.sync.aligned.m8n8.x4.shared.b16 {%0,%1,%2,%3}, [%4];\n"
                 : "=r"(r[0]), "=r"(r[1]), "=r"(r[2]), "=r"(r[3]) : "r"(addr));
}
__device__ __forceinline__ void ldsm_x2t(uint32_t r[2], uint32_t addr) {
    asm volatile("ldmatrix.sync.aligned.m8n8.x2.trans.shared.b16 {%0,%1}, [%2];\n"
                 : "=r"(r[0]), "=r"(r[1]) : "r"(addr));
}
__device__ __forceinline__ void cp16(uint32_t dst, const void* src) {
    asm volatile("cp.async.cg.shared.global [%0], [%1], 16;\n" :: "r"(dst), "l"(src));
}
__device__ __forceinline__ void cp_commit() { asm volatile("cp.async.commit_group;\n"); }
__device__ __forceinline__ void cp_wait1()  { asm volatile("cp.async.wait_group 1;\n" ::: "memory"); }

// ---------------------------------------------------------------------------
// Split kernels: fp32 -> fp16 hi/lo and hi-only
// ---------------------------------------------------------------------------
__global__ void split_kernel(const float* __restrict__ src,
                             __half* __restrict__ dh,
                             __half* __restrict__ dl, int n4) {
    int i = blockIdx.x * blockDim.x + threadIdx.x;
    if (i >= n4) return;
    float4 v = ((const float4*)src)[i];
    __half hx, lx, hy, ly, hz, lz, hw, lw;
    split1(v.x, hx, lx); split1(v.y, hy, ly);
    split1(v.z, hz, lz); split1(v.w, hw, lw);
    uint2 ph, pl;
    ph.x = pack2(hx, hy); ph.y = pack2(hz, hw);
    pl.x = pack2(lx, ly); pl.y = pack2(lz, lw);
    ((uint2*)dh)[i] = ph;
    ((uint2*)dl)[i] = pl;
}

__global__ void split_hi_kernel(const float* __restrict__ src,
                                __half* __restrict__ dh, int n4) {
    int i = blockIdx.x * blockDim.x + threadIdx.x;
    if (i >= n4) return;
    float4 v = ((const float4*)src)[i];
    uint2 ph;
    ph.x = pack2(__float2half_rn(v.x), __float2half_rn(v.y));
    ph.y = pack2(__float2half_rn(v.z), __float2half_rn(v.w));
    ((uint2*)dh)[i] = ph;
}

// ---------------------------------------------------------------------------
// Kernel 1: RPE table MLP + bias gather + qkv bias vector
// ---------------------------------------------------------------------------
__device__ __forceinline__ float coord_feat(int x) {
    float xs = (float)x * (8.0f / 121.0f);
    float v = log1pf(fabsf(xs)) * 0.48089834696298783f; // 1/ln(8)
    return copysignf(v, xs);
}

__global__ void setup_kernel(const float* __restrict__ rpe_w1,
                             const float* __restrict__ rpe_b1,
                             const float* __restrict__ rpe_w2,
                             const float* __restrict__ q_bias,
                             const float* __restrict__ v_bias) {
    __shared__ float sbt[169 * N_HEADS];
    const int tid = threadIdx.x; // 256 threads

    if (tid < 169) {
        int a = tid / 13, b = tid % 13;
        float c0 = coord_feat(b - 6);
        float c1 = coord_feat(a - 6);
        float acc[N_HEADS];
        #pragma unroll
        for (int t = 0; t < N_HEADS; t++) acc[t] = 0.f;
        for (int j = 0; j < 512; j++) {
            float h1 = fmaf(c0, rpe_w1[j], fmaf(c1, rpe_w1[512 + j], rpe_b1[j]));
            h1 = fmaxf(h1, 0.f);
            const float* w2 = rpe_w2 + j * N_HEADS;
            #pragma unroll
            for (int t = 0; t < N_HEADS; t++) acc[t] = fmaf(h1, w2[t], acc[t]);
        }
        #pragma unroll
        for (int t = 0; t < N_HEADS; t++) sbt[tid * N_HEADS + t] = acc[t];
    }

    for (int c = tid; c < QKV_N; c += 256) {
        float v = 0.f;
        if (c < 512)        v = q_bias[c];
        else if (c >= 1024) v = v_bias[c - 1024];
        g_qkvbias[c] = v;
    }
    __syncthreads();

    for (int idx = tid; idx < N_HEADS * NN; idx += 256) {
        int h   = idx / NN;
        int rem = idx % NN;
        int n = rem / N_TOK, m = rem % N_TOK;
        int di = (n / 7) - (m / 7);
        int dj = (n % 7) - (m % 7);
        int r = (dj + 6) * 13 + (di + 6);
        float bt = sbt[r * N_HEADS + h];
        g_pb[idx] = 16.f / (1.f + expf(-bt));
    }
}

// ---------------------------------------------------------------------------
// Pipelined split-fp16 tensor-core GEMM (R11/R14 config — measured best):
// 128 threads = 4 warps, warp tile 64x64, BK=32, 2-stage cp.async ring,
// 2 CTAs/SM. `vstart`: bn < vstart => 3-term; bn >= vstart => 1-term fp16.
// ---------------------------------------------------------------------------
#define SA_STR 40
#define SB_STR 136
#define ASIZE (128 * SA_STR)
#define BSIZE (32 * SB_STR)
#define SMEM_BYTES ((2 * (2 * ASIZE + 2 * BSIZE)) * 2)  // 75776 B

__device__ __forceinline__ void gemm_issue(
    int it, int buf, int iters, int tid, int terms,
    const __half* Ah, const __half* Al,
    const __half* Bh, const __half* Bl,
    size_t Abase, int nblk, int N, int K,
    uint32_t sAh32, uint32_t sAl32, uint32_t sBh32, uint32_t sBl32)
{
    if (it < iters) {
        const int k0 = it * 32;
        const uint32_t aoff = (uint32_t)buf * (ASIZE * 2);
        const uint32_t boff = (uint32_t)buf * (BSIZE * 2);
        #pragma unroll
        for (int p = 0; p < 4; p++) {
            int c = tid + p * 128;
            int row = c >> 2, seg = (c & 3) * 8;
            size_t go = Abase + (size_t)row * K + k0 + seg;
            uint32_t ds = (uint32_t)(row * SA_STR + seg) * 2;
            cp16(sAh32 + aoff + ds, Ah + go);
            if (terms == 3) cp16(sAl32 + aoff + ds, Al + go);
        }
        #pragma unroll
        for (int p = 0; p < 4; p++) {
            int c = tid + p * 128;
            int row = c >> 4, seg = (c & 15) * 8;
            size_t go = (size_t)(k0 + row) * N + nblk + seg;
            uint32_t ds = (uint32_t)(row * SB_STR + seg) * 2;
            cp16(sBh32 + boff + ds, Bh + go);
            if (terms == 3) cp16(sBl32 + boff + ds, Bl + go);
        }
    }
    cp_commit();
}

__device__ __forceinline__ void gemm_core(
    const __half* __restrict__ Ah, const __half* __restrict__ Al,
    const __half* __restrict__ Bh, const __half* __restrict__ Bl,
    const float* __restrict__ bias, float* __restrict__ C, int N, int K,
    int vstart)
{
    extern __shared__ __half smem[];
    __half* sAh = smem;
    __half* sAl = sAh + 2 * ASIZE;
    __half* sBh = sAl + 2 * ASIZE;
    __half* sBl = sBh + 2 * BSIZE;

    const int tid  = threadIdx.x;          // 128 threads
    const int bm   = blockIdx.y, bn = blockIdx.x;
    const int terms = (bn < vstart) ? 3 : 1;
    const int lane = tid & 31;
    const int w    = tid >> 5;              // 0..3
    const int wm   = (w >> 1) * 64;
    const int wn   = (w & 1) * 64;
    const int l15  = lane & 15;
    const int lhi8 = (lane >> 4) * 8;

    const size_t Abase = (size_t)bm * 128 * K;
    const int nblk = bn * 128;

    const uint32_t sAh32 = (uint32_t)__cvta_generic_to_shared(sAh);
    const uint32_t sAl32 = (uint32_t)__cvta_generic_to_shared(sAl);
    const uint32_t sBh32 = (uint32_t)__cvta_generic_to_shared(sBh);
    const uint32_t sBl32 = (uint32_t)__cvta_generic_to_shared(sBl);

    float acc[4][8][4];
    #pragma unroll
    for (int mi = 0; mi < 4; mi++)
        #pragma unroll
        for (int ni = 0; ni < 8; ni++)
            #pragma unroll
            for (int r = 0; r < 4; r++) acc[mi][ni][r] = 0.f;

    const int iters = K / 32;
    gemm_issue(0, 0, iters, tid, terms, Ah, Al, Bh, Bl, Abase, nblk, N, K,
               sAh32, sAl32, sBh32, sBl32);
    gemm_issue(1, 1, iters, tid, terms, Ah, Al, Bh, Bl, Abase, nblk, N, K,
               sAh32, sAl32, sBh32, sBl32);

    for (int it = 0; it < iters; it++) {
        const int buf = it & 1;
        cp_wait1();
        __syncthreads();

        const uint32_t aoff = (uint32_t)buf * (ASIZE * 2);
        const uint32_t boff = (uint32_t)buf * (BSIZE * 2);

        if (terms == 3) {
            #pragma unroll
            for (int ks = 0; ks < 32; ks += 16) {
                uint32_t bh[8][2], bl[8][2];
                #pragma unroll
                for (int ni = 0; ni < 8; ni++) {
                    uint32_t ds = (uint32_t)((ks + l15) * SB_STR + wn + ni * 8) * 2;
                    ldsm_x2t(bh[ni], sBh32 + boff + ds);
                    ldsm_x2t(bl[ni], sBl32 + boff + ds);
                }
                #pragma unroll
                for (int mi = 0; mi < 4; mi++) {
                    uint32_t ds = (uint32_t)((wm + mi * 16 + l15) * SA_STR + ks + lhi8) * 2;
                    uint32_t ah[4], al[4];
                    ldsm_x4(ah, sAh32 + aoff + ds);
                    ldsm_x4(al, sAl32 + aoff + ds);
                    #pragma unroll
                    for (int ni = 0; ni < 8; ni++) {
                        mma_f16(acc[mi][ni], ah, bh[ni]);
                        mma_f16(acc[mi][ni], ah, bl[ni]);
                        mma_f16(acc[mi][ni], al, bh[ni]);
                    }
                }
            }
        } else {
            #pragma unroll
            for (int ks = 0; ks < 32; ks += 16) {
                uint32_t bh[8][2];
                #pragma unroll
                for (int ni = 0; ni < 8; ni++) {
                    uint32_t ds = (uint32_t)((ks + l15) * SB_STR + wn + ni * 8) * 2;
                    ldsm_x2t(bh[ni], sBh32 + boff + ds);
                }
                #pragma unroll
                for (int mi = 0; mi < 4; mi++) {
                    uint32_t ds = (uint32_t)((wm + mi * 16 + l15) * SA_STR + ks + lhi8) * 2;
                    uint32_t ah[4];
                    ldsm_x4(ah, sAh32 + aoff + ds);
                    #pragma unroll
                    for (int ni = 0; ni < 8; ni++)
                        mma_f16(acc[mi][ni], ah, bh[ni]);
                }
            }
        }
        __syncthreads();
        gemm_issue(it + 2, buf, iters, tid, terms, Ah, Al, Bh, Bl, Abase, nblk, N, K,
                   sAh32, sAl32, sBh32, sBl32);
    }

    const int g  = lane >> 2;
    const int t2 = (lane & 3) * 2;
    #pragma unroll
    for (int mi = 0; mi < 4; mi++) {
        int row = bm * 128 + wm + mi * 16 + g;
        #pragma unroll
        for (int ni = 0; ni < 8; ni++) {
            int col = bn * 128 + wn + ni * 8 + t2;
            float b0 = bias[col], b1 = bias[col + 1];
            float2 o0 = make_float2(acc[mi][ni][0] + b0, acc[mi][ni][1] + b1);
            float2 o1 = make_float2(acc[mi][ni][2] + b0, acc[mi][ni][3] + b1);
            *(float2*)(C + (size_t)row * N + col)       = o0;
            *(float2*)(C + (size_t)(row + 8) * N + col) = o1;
        }
    }
}

__global__ void __launch_bounds__(128, 2)
qkv_gemm_kernel() {
    // N-tiles 0..7 are q,k (3-term); tiles 8..11 are v (1-term fp16)
    gemm_core(g_xh, g_xl, g_qwh, g_qwl, g_qkvbias, g_qkv, QKV_N, C_DIM, 8);
}

__global__ void __launch_bounds__(128, 2)
proj_gemm_kernel(const float* __restrict__ proj_b, float* __restrict__ out) {
    // final projection: 1-term fp16 (lo operands never read)
    gemm_core(g_aoh, g_aoh, g_pwh, g_pwh, proj_b, out, C_DIM, C_DIM, 0);
}

// ---------------------------------------------------------------------------
// Kernel 3: tensor-core attention per (window, head).
// QK^T: 3-term split fp16. PV: 1-term fp16. Output: hi-only fp16.
// ---------------------------------------------------------------------------
#define ATT_QH  0
#define ATT_QL  5120
#define ATT_KTH 10240
#define ATT_KTL 14848
#define ATT_VH  19456
#define ATT_SS  29696
#define ATT_TOT (29696 + 64 * 66 * 4)   // 46592 B
#define ATT_PH  0                        // P hi overlays dead Q region

__global__ void __launch_bounds__(256, 2)
attn_kernel(const float* __restrict__ mask, const float* __restrict__ logit_scale) {
    const int b = blockIdx.x >> 4;
    const int h = blockIdx.x & 15;
    const int tid  = threadIdx.x;
    const int lane = tid & 31;
    const int w    = tid >> 5;

    __shared__ __align__(16) char sm[ATT_TOT];
    __half* sQh  = (__half*)(sm + ATT_QH);
    __half* sQl  = (__half*)(sm + ATT_QL);
    __half* sKth = (__half*)(sm + ATT_KTH);
    __half* sKtl = (__half*)(sm + ATT_KTL);
    __half* sVh  = (__half*)(sm + ATT_VH);
    __half* sPh  = (__half*)(sm + ATT_PH);
    float* sS = (float*)(sm + ATT_SS);
    const uint32_t smb = (uint32_t)__cvta_generic_to_shared(sm);

    // ---- Phase 1: stage q,k fp32; V hi-only fp16 ----
    const float* base = g_qkv + (size_t)b * N_TOK * QKV_N + h * HD;
    #pragma unroll
    for (int p = 0; p < 8; p++) {
        int idx = tid + p * 256;
        int r = idx >> 5, d = idx & 31;
        float qv = 0.f, kv = 0.f, vv = 0.f;
        if (r < N_TOK) {
            const float* pp = base + (size_t)r * QKV_N + d;
            qv = pp[0]; kv = pp[512]; vv = pp[1024];
        }
        sS[r * 66 + d]      = qv;
        sS[r * 66 + 32 + d] = kv;
        sVh[r * 40 + d] = __float2half_rn(vv);
    }
    __syncthreads();

    // ---- Phase 2: normalize rows (uniform), split Q / K^T ----
    {
        const int r  = tid >> 2;
        const int qd = (tid & 3) * 8;
        float qv[8], kv[8];
        float sq = 0.f, sk = 0.f;
        #pragma unroll
        for (int j = 0; j < 8; j++) {
            qv[j] = sS[r * 66 + qd + j];
            kv[j] = sS[r * 66 + 32 + qd + j];
            sq = fmaf(qv[j], qv[j], sq);
            sk = fmaf(kv[j], kv[j], sk);
        }
        sq += __shfl_xor_sync(0xffffffff, sq, 1);
        sq += __shfl_xor_sync(0xffffffff, sq, 2);
        sk += __shfl_xor_sync(0xffffffff, sk, 1);
        sk += __shfl_xor_sync(0xffffffff, sk, 2);
        float hs  = __expf(fminf(logit_scale[h], 4.605170185988091f));
        float qsc = rsqrtf(fmaxf(sq, 1e-12f)) * hs;
        float ksc = rsqrtf(fmaxf(sk, 1e-12f));
        #pragma unroll
        for (int j = 0; j < 8; j += 2) {
            __half h0, l0, h1, l1;
            split1(qv[j] * qsc, h0, l0);
            split1(qv[j + 1] * qsc, h1, l1);
            *(uint32_t*)&sQh[r * 40 + qd + j] = pack2(h0, h1);
            *(uint32_t*)&sQl[r * 40 + qd + j] = pack2(l0, l1);
        }
        #pragma unroll
        for (int j = 0; j < 8; j++) {
            __half kh, kl;
            split1(kv[j] * ksc, kh, kl);
            sKth[(qd + j) * 72 + r] = kh;
            sKtl[(qd + j) * 72 + r] = kl;
        }
    }
    __syncthreads();

    // ---- Phase 3: S = Qn @ Kn^T (3-term) ----
    {
        const int m0  = (w & 3) * 16;
        const int n0  = (w >> 2) * 32;
        const int l15 = lane & 15;
        const int lhi8 = (lane >> 4) * 8;
        float acc[4][4];
        #pragma unroll
        for (int ni = 0; ni < 4; ni++)
            #pragma unroll
            for (int r = 0; r < 4; r++) acc[ni][r] = 0.f;

        #pragma unroll
        for (int ks = 0; ks < 32; ks += 16) {
            uint32_t ah[4], al[4];
            uint32_t dsA = (uint32_t)(ATT_QH) + (uint32_t)((m0 + l15) * 40 + ks + lhi8) * 2;
            ldsm_x4(ah, smb + dsA);
            ldsm_x4(al, smb + dsA + (ATT_QL - ATT_QH));
            #pragma unroll
            for (int ni = 0; ni < 4; ni++) {
                uint32_t bh[2], bl[2];
                uint32_t dsB = (uint32_t)(ATT_KTH) + (uint32_t)((ks + l15) * 72 + n0 + ni * 8) * 2;
                ldsm_x2t(bh, smb + dsB);
                ldsm_x2t(bl, smb + dsB + (ATT_KTL - ATT_KTH));
                mma_f16(acc[ni], ah, bh);
                mma_f16(acc[ni], ah, bl);
                mma_f16(acc[ni], al, bh);
            }
        }
        const int g  = lane >> 2;
        const int t2 = (lane & 3) * 2;
        #pragma unroll
        for (int ni = 0; ni < 4; ni++) {
            int c = n0 + ni * 8 + t2;
            *(float2*)&sS[(m0 + g) * 66 + c]     = make_float2(acc[ni][0], acc[ni][1]);
            *(float2*)&sS[(m0 + 8 + g) * 66 + c] = make_float2(acc[ni][2], acc[ni][3]);
        }
    }
    __syncthreads();

    // ---- Phase 4: softmax (uniform); P hi-only fp16 ----
    {
        const int r  = tid >> 2;
        const int c0 = (tid & 3) * 16;
        const int rr = (r < N_TOK) ? r : 0;
        const int ww = b & (NWMASK - 1);
        const float* pbr = g_pb + h * NN + rr * N_TOK;
        const float* mr  = mask + (size_t)ww * NN + rr * N_TOK;
        float vals[16];
        float mx = -1e30f;
        #pragma unroll
        for (int i = 0; i < 16; i++) {
            int m = c0 + i;
            float v = -1e30f;
            if (m < N_TOK) v = sS[r * 66 + m] + pbr[m] + mr[m];
            vals[i] = v;
            mx = fmaxf(mx, v);
        }
        mx = fmaxf(mx, __shfl_xor_sync(0xffffffff, mx, 1));
        mx = fmaxf(mx, __shfl_xor_sync(0xffffffff, mx, 2));
        float sum = 0.f;
        #pragma unroll
        for (int i = 0; i < 16; i++) {
            float e = (c0 + i < N_TOK) ? __expf(vals[i] - mx) : 0.f;
            vals[i] = e;
            sum += e;
        }
        sum += __shfl_xor_sync(0xffffffff, sum, 1);
        sum += __shfl_xor_sync(0xffffffff, sum, 2);
        float inv = 1.f / sum;
        #pragma unroll
        for (int i = 0; i < 16; i += 2) {
            *(uint32_t*)&sPh[r * 72 + c0 + i] =
                pack2(__float2half_rn(vals[i] * inv), __float2half_rn(vals[i + 1] * inv));
        }
    }
    __syncthreads();

    // ---- Phase 5: O = P @ V (1-term); hi-only output ----
    {
        const int m0  = (w & 3) * 16;
        const int n0  = (w >> 2) * 16;
        const int l15 = lane & 15;
        const int lhi8 = (lane >> 4) * 8;
        float acc[2][4];
        #pragma unroll
        for (int ni = 0; ni < 2; ni++)
            #pragma unroll
            for (int r = 0; r < 4; r++) acc[ni][r] = 0.f;

        #pragma unroll
        for (int ks = 0; ks < 64; ks += 16) {
            uint32_t ah[4];
            uint32_t dsA = (uint32_t)(ATT_PH) + (uint32_t)((m0 + l15) * 72 + ks + lhi8) * 2;
            ldsm_x4(ah, smb + dsA);
            #pragma unroll
            for (int ni = 0; ni < 2; ni++) {
                uint32_t bh[2];
                uint32_t dsB = (uint32_t)(ATT_VH) + (uint32_t)((ks + l15) * 40 + n0 + ni * 8) * 2;
                ldsm_x2t(bh, smb + dsB);
                mma_f16(acc[ni], ah, bh);
            }
        }
        const int g  = lane >> 2;
        const int t2 = (lane & 3) * 2;
        #pragma unroll
        for (int ni = 0; ni < 2; ni++) {
            int col  = h * HD + n0 + ni * 8 + t2;
            int row0 = m0 + g, row1 = m0 + 8 + g;
            if (row0 < N_TOK) {
                size_t o = ((size_t)b * N_TOK + row0) * C_DIM + col;
                *(uint32_t*)(g_aoh + o) =
                    pack2(__float2half_rn(acc[ni][0]), __float2half_rn(acc[ni][1]));
            }
            if (row1 < N_TOK) {
                size_t o = ((size_t)b * N_TOK + row1) * C_DIM + col;
                *(uint32_t*)(g_aoh + o) =
                    pack2(__float2half_rn(acc[ni][2]), __float2half_rn(acc[ni][3]));
            }
        }
    }
}

// ---------------------------------------------------------------------------
// Launch
// ---------------------------------------------------------------------------
extern "C" void kernel_launch(void* const* d_in, const int* in_sizes, int n_in,
                              void* d_out, int out_size) {
    const float* x           = (const float*)d_in[0];
    const float* mask        = (const float*)d_in[1];
    const float* qkv_w       = (const float*)d_in[2];
    const float* q_bias      = (const float*)d_in[3];
    const float* v_bias      = (const float*)d_in[4];
    const float* logit_scale = (const float*)d_in[5];
    const float* rpe_w1      = (const float*)d_in[6];
    const float* rpe_b1      = (const float*)d_in[7];
    const float* rpe_w2      = (const float*)d_in[8];
    const float* proj_w      = (const float*)d_in[9];
    const float* proj_b      = (const float*)d_in[10];
    float* out = (float*)d_out;

    cudaFuncSetAttribute(qkv_gemm_kernel,
                         cudaFuncAttributeMaxDynamicSharedMemorySize, SMEM_BYTES);
    cudaFuncSetAttribute(proj_gemm_kernel,
                         cudaFuncAttributeMaxDynamicSharedMemorySize, SMEM_BYTES);

    __half *xh, *xl, *qwh, *qwl, *pwh;
    cudaGetSymbolAddress((void**)&xh,  g_xh);
    cudaGetSymbolAddress((void**)&xl,  g_xl);
    cudaGetSymbolAddress((void**)&qwh, g_qwh);
    cudaGetSymbolAddress((void**)&qwl, g_qwl);
    cudaGetSymbolAddress((void**)&pwh, g_pwh);

    setup_kernel<<<1, 256>>>(rpe_w1, rpe_b1, rpe_w2, q_bias, v_bias);

    {
        int n4 = M_ROWS * C_DIM / 4;
        split_kernel<<<(n4 + 255) / 256, 256>>>(x, xh, xl, n4);
    }
    {
        int n4 = C_DIM * QKV_N / 4;
        split_kernel<<<(n4 + 255) / 256, 256>>>(qkv_w, qwh, qwl, n4);
    }
    {
        int n4 = C_DIM * C_DIM / 4;
        split_hi_kernel<<<(n4 + 255) / 256, 256>>>(proj_w, pwh, n4);
    }

    // QKV: [100352,512] @ [512,1536], 128-thread blocks (R11 config)
    qkv_gemm_kernel<<<dim3(QKV_N / 128, M_ROWS / 128), 128, SMEM_BYTES>>>();

    attn_kernel<<<BWIN * N_HEADS, 256>>>(mask, logit_scale);

    // proj: [100352,512] @ [512,512] -> d_out
    proj_gemm_kernel<<<dim3(C_DIM / 128, M_ROWS / 128), 128, SMEM_BYTES>>>(proj_b, out);
}

// round 17
// speedup vs baseline: 1.0926x; 1.0327x over previous
#include <cuda_runtime.h>
#include <cuda_fp16.h>
#include <math.h>
#include <stdint.h>

// ---------------------------------------------------------------------------
// Problem constants
// ---------------------------------------------------------------------------
#define BWIN    2048
#define N_TOK   49
#define C_DIM   512
#define N_HEADS 16
#define HD      32
#define QKV_N   1536
#define M_ROWS  (BWIN * N_TOK)     // 100352 = 784 * 128
#define NN      (N_TOK * N_TOK)    // 2401
#define NWMASK  64

// ---------------------------------------------------------------------------
// Scratch (static device globals; zero-initialized => padding rows stay 0)
// ---------------------------------------------------------------------------
__device__ __half g_xh[(size_t)M_ROWS * C_DIM];      // x split hi [M,K]
__device__ __half g_xl[(size_t)M_ROWS * C_DIM];      // x split lo
__device__ __half g_qwh[C_DIM * QKV_N];              // qkv_w hi  [K,N]
__device__ __half g_qwl[C_DIM * QKV_N];              // qkv_w lo
__device__ __half g_pwh[C_DIM * C_DIM];              // proj_w hi [K,N]
// normalized / split attention operands, token-padded 49->64
__device__ __half g_qh[(size_t)BWIN * N_HEADS * 64 * 32];   // [b][h][tok][dim]
__device__ __half g_ql[(size_t)BWIN * N_HEADS * 64 * 32];
__device__ __half g_kth[(size_t)BWIN * N_HEADS * 32 * 64];  // [b][h][dim][tok]
__device__ __half g_ktl[(size_t)BWIN * N_HEADS * 32 * 64];
__device__ __half g_vh[(size_t)BWIN * N_HEADS * 64 * 32];   // [b][h][tok][dim]
__device__ __half g_aoh[(size_t)M_ROWS * C_DIM];     // attn out hi
__device__ float g_pb [N_HEADS * NN];
__device__ float g_qkvbias[QKV_N];

// ---------------------------------------------------------------------------
// Helpers
// ---------------------------------------------------------------------------
__device__ __forceinline__ uint32_t pack2(__half a, __half b) {
    __half2 v = __halves2half2(a, b);
    return *(uint32_t*)&v;
}
__device__ __forceinline__ void split1(float v, __half& h, __half& l) {
    h = __float2half_rn(v);
    l = __float2half_rn(v - __half2float(h));
}

__device__ __forceinline__ void mma_f16(float d[4],
                                        const uint32_t a[4],
                                        const uint32_t b[2]) {
    asm volatile(
        "mma.sync.aligned.m16n8k16.row.col.f32.f16.f16.f32 "
        "{%0,%1,%2,%3}, {%4,%5,%6,%7}, {%8,%9}, {%0,%1,%2,%3};\n"
        : "+f"(d[0]), "+f"(d[1]), "+f"(d[2]), "+f"(d[3])
        : "r"(a[0]), "r"(a[1]), "r"(a[2]), "r"(a[3]), "r"(b[0]), "r"(b[1]));
}
__device__ __forceinline__ void ldsm_x4(uint32_t r[4], uint32_t addr) {
    asm volatile("ldmatrix.sync.aligned.m8n8.x4.shared.b16 {%0,%1,%2,%3}, [%4];\n"
                 : "=r"(r[0]), "=r"(r[1]), "=r"(r[2]), "=r"(r[3]) : "r"(addr));
}
__device__ __forceinline__ void ldsm_x2t(uint32_t r[2], uint32_t addr) {
    asm volatile("ldmatrix.sync.aligned.m8n8.x2.trans.shared.b16 {%0,%1}, [%2];\n"
                 : "=r"(r[0]), "=r"(r[1]) : "r"(addr));
}
__device__ __forceinline__ void cp16(uint32_t dst, const void* src) {
    asm volatile("cp.async.cg.shared.global [%0], [%1], 16;\n" :: "r"(dst), "l"(src));
}
__device__ __forceinline__ void cp_commit() { asm volatile("cp.async.commit_group;\n"); }
__device__ __forceinline__ void cp_wait1()  { asm volatile("cp.async.wait_group 1;\n" ::: "memory"); }
__device__ __forceinline__ void cp_wait0()  { asm volatile("cp.async.wait_group 0;\n" ::: "memory"); }

// ---------------------------------------------------------------------------
// Split kernels
// ---------------------------------------------------------------------------
__global__ void split_kernel(const float* __restrict__ src,
                             __half* __restrict__ dh,
                             __half* __restrict__ dl, int n4) {
    int i = blockIdx.x * blockDim.x + threadIdx.x;
    if (i >= n4) return;
    float4 v = ((const float4*)src)[i];
    __half hx, lx, hy, ly, hz, lz, hw, lw;
    split1(v.x, hx, lx); split1(v.y, hy, ly);
    split1(v.z, hz, lz); split1(v.w, hw, lw);
    uint2 ph, pl;
    ph.x = pack2(hx, hy); ph.y = pack2(hz, hw);
    pl.x = pack2(lx, ly); pl.y = pack2(lz, lw);
    ((uint2*)dh)[i] = ph;
    ((uint2*)dl)[i] = pl;
}

__global__ void split_hi_kernel(const float* __restrict__ src,
                                __half* __restrict__ dh, int n4) {
    int i = blockIdx.x * blockDim.x + threadIdx.x;
    if (i >= n4) return;
    float4 v = ((const float4*)src)[i];
    uint2 ph;
    ph.x = pack2(__float2half_rn(v.x), __float2half_rn(v.y));
    ph.y = pack2(__float2half_rn(v.z), __float2half_rn(v.w));
    ((uint2*)dh)[i] = ph;
}

// ---------------------------------------------------------------------------
// Kernel 1: RPE table MLP + bias gather + qkv bias vector
// ---------------------------------------------------------------------------
__device__ __forceinline__ float coord_feat(int x) {
    float xs = (float)x * (8.0f / 121.0f);
    float v = log1pf(fabsf(xs)) * 0.48089834696298783f; // 1/ln(8)
    return copysignf(v, xs);
}

__global__ void setup_kernel(const float* __restrict__ rpe_w1,
                             const float* __restrict__ rpe_b1,
                             const float* __restrict__ rpe_w2,
                             const float* __restrict__ q_bias,
                             const float* __restrict__ v_bias) {
    __shared__ float sbt[169 * N_HEADS];
    const int tid = threadIdx.x; // 256 threads

    if (tid < 169) {
        int a = tid / 13, b = tid % 13;
        float c0 = coord_feat(b - 6);
        float c1 = coord_feat(a - 6);
        float acc[N_HEADS];
        #pragma unroll
        for (int t = 0; t < N_HEADS; t++) acc[t] = 0.f;
        for (int j = 0; j < 512; j++) {
            float h1 = fmaf(c0, rpe_w1[j], fmaf(c1, rpe_w1[512 + j], rpe_b1[j]));
            h1 = fmaxf(h1, 0.f);
            const float* w2 = rpe_w2 + j * N_HEADS;
            #pragma unroll
            for (int t = 0; t < N_HEADS; t++) acc[t] = fmaf(h1, w2[t], acc[t]);
        }
        #pragma unroll
        for (int t = 0; t < N_HEADS; t++) sbt[tid * N_HEADS + t] = acc[t];
    }

    for (int c = tid; c < QKV_N; c += 256) {
        float v = 0.f;
        if (c < 512)        v = q_bias[c];
        else if (c >= 1024) v = v_bias[c - 1024];
        g_qkvbias[c] = v;
    }
    __syncthreads();

    for (int idx = tid; idx < N_HEADS * NN; idx += 256) {
        int h   = idx / NN;
        int rem = idx % NN;
        int n = rem / N_TOK, m = rem % N_TOK;
        int di = (n / 7) - (m / 7);
        int dj = (n % 7) - (m % 7);
        int r = (dj + 6) * 13 + (di + 6);
        float bt = sbt[r * N_HEADS + h];
        g_pb[idx] = 16.f / (1.f + expf(-bt));
    }
}

// ---------------------------------------------------------------------------
// Pipelined split-fp16 tensor-core GEMM (R11 config). EPI selects epilogue:
//   EPI=0: plain fp32 store with bias (proj -> d_out)
//   EPI=1: QKV fused epilogue — +bias, per-head l2-normalize q (x logit
//          scale) and k on exact accumulators, split fp16, write q/k^T/v.
// `vstart`: bn < vstart => 3-term; else 1-term fp16.
// ---------------------------------------------------------------------------
#define SA_STR 40
#define SB_STR 136
#define ASIZE (128 * SA_STR)
#define BSIZE (32 * SB_STR)
#define SMEM_BYTES ((2 * (2 * ASIZE + 2 * BSIZE)) * 2)  // 75776 B

__device__ __forceinline__ void gemm_issue(
    int it, int buf, int iters, int tid, int terms,
    const __half* Ah, const __half* Al,
    const __half* Bh, const __half* Bl,
    size_t Abase, int nblk, int N, int K,
    uint32_t sAh32, uint32_t sAl32, uint32_t sBh32, uint32_t sBl32)
{
    if (it < iters) {
        const int k0 = it * 32;
        const uint32_t aoff = (uint32_t)buf * (ASIZE * 2);
        const uint32_t boff = (uint32_t)buf * (BSIZE * 2);
        #pragma unroll
        for (int p = 0; p < 4; p++) {
            int c = tid + p * 128;
            int row = c >> 2, seg = (c & 3) * 8;
            size_t go = Abase + (size_t)row * K + k0 + seg;
            uint32_t ds = (uint32_t)(row * SA_STR + seg) * 2;
            cp16(sAh32 + aoff + ds, Ah + go);
            if (terms == 3) cp16(sAl32 + aoff + ds, Al + go);
        }
        #pragma unroll
        for (int p = 0; p < 4; p++) {
            int c = tid + p * 128;
            int row = c >> 4, seg = (c & 15) * 8;
            size_t go = (size_t)(k0 + row) * N + nblk + seg;
            uint32_t ds = (uint32_t)(row * SB_STR + seg) * 2;
            cp16(sBh32 + boff + ds, Bh + go);
            if (terms == 3) cp16(sBl32 + boff + ds, Bl + go);
        }
    }
    cp_commit();
}

template <int EPI>
__device__ __forceinline__ void gemm_core(
    const __half* __restrict__ Ah, const __half* __restrict__ Al,
    const __half* __restrict__ Bh, const __half* __restrict__ Bl,
    const float* __restrict__ bias, float* __restrict__ C, int N, int K,
    int vstart, const float* __restrict__ logit_scale)
{
    extern __shared__ __half smem[];
    __half* sAh = smem;
    __half* sAl = sAh + 2 * ASIZE;
    __half* sBh = sAl + 2 * ASIZE;
    __half* sBl = sBh + 2 * BSIZE;

    const int tid  = threadIdx.x;          // 128 threads
    const int bm   = blockIdx.y, bn = blockIdx.x;
    const int terms = (bn < vstart) ? 3 : 1;
    const int lane = tid & 31;
    const int w    = tid >> 5;              // 0..3
    const int wm   = (w >> 1) * 64;
    const int wn   = (w & 1) * 64;
    const int l15  = lane & 15;
    const int lhi8 = (lane >> 4) * 8;

    const size_t Abase = (size_t)bm * 128 * K;
    const int nblk = bn * 128;

    const uint32_t sAh32 = (uint32_t)__cvta_generic_to_shared(sAh);
    const uint32_t sAl32 = (uint32_t)__cvta_generic_to_shared(sAl);
    const uint32_t sBh32 = (uint32_t)__cvta_generic_to_shared(sBh);
    const uint32_t sBl32 = (uint32_t)__cvta_generic_to_shared(sBl);

    float acc[4][8][4];
    #pragma unroll
    for (int mi = 0; mi < 4; mi++)
        #pragma unroll
        for (int ni = 0; ni < 8; ni++)
            #pragma unroll
            for (int r = 0; r < 4; r++) acc[mi][ni][r] = 0.f;

    const int iters = K / 32;
    gemm_issue(0, 0, iters, tid, terms, Ah, Al, Bh, Bl, Abase, nblk, N, K,
               sAh32, sAl32, sBh32, sBl32);
    gemm_issue(1, 1, iters, tid, terms, Ah, Al, Bh, Bl, Abase, nblk, N, K,
               sAh32, sAl32, sBh32, sBl32);

    for (int it = 0; it < iters; it++) {
        const int buf = it & 1;
        cp_wait1();
        __syncthreads();

        const uint32_t aoff = (uint32_t)buf * (ASIZE * 2);
        const uint32_t boff = (uint32_t)buf * (BSIZE * 2);

        if (terms == 3) {
            #pragma unroll
            for (int ks = 0; ks < 32; ks += 16) {
                uint32_t bh[8][2], bl[8][2];
                #pragma unroll
                for (int ni = 0; ni < 8; ni++) {
                    uint32_t ds = (uint32_t)((ks + l15) * SB_STR + wn + ni * 8) * 2;
                    ldsm_x2t(bh[ni], sBh32 + boff + ds);
                    ldsm_x2t(bl[ni], sBl32 + boff + ds);
                }
                #pragma unroll
                for (int mi = 0; mi < 4; mi++) {
                    uint32_t ds = (uint32_t)((wm + mi * 16 + l15) * SA_STR + ks + lhi8) * 2;
                    uint32_t ah[4], al[4];
                    ldsm_x4(ah, sAh32 + aoff + ds);
                    ldsm_x4(al, sAl32 + aoff + ds);
                    #pragma unroll
                    for (int ni = 0; ni < 8; ni++) {
                        mma_f16(acc[mi][ni], ah, bh[ni]);
                        mma_f16(acc[mi][ni], ah, bl[ni]);
                        mma_f16(acc[mi][ni], al, bh[ni]);
                    }
                }
            }
        } else {
            #pragma unroll
            for (int ks = 0; ks < 32; ks += 16) {
                uint32_t bh[8][2];
                #pragma unroll
                for (int ni = 0; ni < 8; ni++) {
                    uint32_t ds = (uint32_t)((ks + l15) * SB_STR + wn + ni * 8) * 2;
                    ldsm_x2t(bh[ni], sBh32 + boff + ds);
                }
                #pragma unroll
                for (int mi = 0; mi < 4; mi++) {
                    uint32_t ds = (uint32_t)((wm + mi * 16 + l15) * SA_STR + ks + lhi8) * 2;
                    uint32_t ah[4];
                    ldsm_x4(ah, sAh32 + aoff + ds);
                    #pragma unroll
                    for (int ni = 0; ni < 8; ni++)
                        mma_f16(acc[mi][ni], ah, bh[ni]);
                }
            }
        }
        __syncthreads();
        gemm_issue(it + 2, buf, iters, tid, terms, Ah, Al, Bh, Bl, Abase, nblk, N, K,
                   sAh32, sAl32, sBh32, sBl32);
    }

    const int g  = lane >> 2;
    const int t2 = (lane & 3) * 2;

    // add bias
    #pragma unroll
    for (int mi = 0; mi < 4; mi++)
        #pragma unroll
        for (int ni = 0; ni < 8; ni++) {
            int col = nblk + wn + ni * 8 + t2;
            float b0 = bias[col], b1 = bias[col + 1];
            acc[mi][ni][0] += b0; acc[mi][ni][1] += b1;
            acc[mi][ni][2] += b0; acc[mi][ni][3] += b1;
        }

    if (EPI == 0) {
        #pragma unroll
        for (int mi = 0; mi < 4; mi++) {
            int row = bm * 128 + wm + mi * 16 + g;
            #pragma unroll
            for (int ni = 0; ni < 8; ni++) {
                int col = nblk + wn + ni * 8 + t2;
                *(float2*)(C + (size_t)row * N + col) =
                    make_float2(acc[mi][ni][0], acc[mi][ni][1]);
                *(float2*)(C + (size_t)(row + 8) * N + col) =
                    make_float2(acc[mi][ni][2], acc[mi][ni][3]);
            }
        }
    } else {
        // ---- QKV fused epilogue ----
        if (bn < 8) {
            const bool isq = (bn < 4);
            const int colbase = nblk + wn - (isq ? 0 : 512);
            #pragma unroll
            for (int half = 0; half < 2; half++) {
                const int h = (colbase >> 5) + half;
                const float hs = isq
                    ? __expf(fminf(logit_scale[h], 4.605170185988091f)) : 1.f;
                #pragma unroll
                for (int mi = 0; mi < 4; mi++) {
                    #pragma unroll
                    for (int rh = 0; rh < 2; rh++) {
                        float s = 0.f;
                        #pragma unroll
                        for (int nj = 0; nj < 4; nj++) {
                            float a0 = acc[mi][half * 4 + nj][rh * 2];
                            float a1 = acc[mi][half * 4 + nj][rh * 2 + 1];
                            s = fmaf(a0, a0, fmaf(a1, a1, s));
                        }
                        s += __shfl_xor_sync(0xffffffffu, s, 1);
                        s += __shfl_xor_sync(0xffffffffu, s, 2);
                        const float sc = rsqrtf(fmaxf(s, 1e-12f)) * hs;
                        const int m = bm * 128 + wm + mi * 16 + g + rh * 8;
                        const int b = m / 49, n = m - b * 49;
                        if (isq) {
                            size_t base = (((size_t)b * 16 + h) * 64 + n) * 32;
                            #pragma unroll
                            for (int nj = 0; nj < 4; nj++) {
                                int dim = nj * 8 + t2;
                                __half h0, l0, h1, l1;
                                split1(acc[mi][half * 4 + nj][rh * 2] * sc, h0, l0);
                                split1(acc[mi][half * 4 + nj][rh * 2 + 1] * sc, h1, l1);
                                *(uint32_t*)(g_qh + base + dim) = pack2(h0, h1);
                                *(uint32_t*)(g_ql + base + dim) = pack2(l0, l1);
                            }
                        } else {
                            size_t base = ((size_t)b * 16 + h) * 2048 + n;  // [32][64]
                            #pragma unroll
                            for (int nj = 0; nj < 4; nj++) {
                                int dim = nj * 8 + t2;
                                __half h0, l0, h1, l1;
                                split1(acc[mi][half * 4 + nj][rh * 2] * sc, h0, l0);
                                split1(acc[mi][half * 4 + nj][rh * 2 + 1] * sc, h1, l1);
                                g_kth[base + (size_t)dim * 64]       = h0;
                                g_ktl[base + (size_t)dim * 64]       = l0;
                                g_kth[base + (size_t)(dim + 1) * 64] = h1;
                                g_ktl[base + (size_t)(dim + 1) * 64] = l1;
                            }
                        }
                    }
                }
            }
        } else {
            const int colbase = nblk + wn - 1024;
            #pragma unroll
            for (int mi = 0; mi < 4; mi++) {
                #pragma unroll
                for (int rh = 0; rh < 2; rh++) {
                    const int m = bm * 128 + wm + mi * 16 + g + rh * 8;
                    const int b = m / 49, n = m - b * 49;
                    #pragma unroll
                    for (int ni = 0; ni < 8; ni++) {
                        int c = colbase + ni * 8 + t2;
                        int h = c >> 5, dim = c & 31;
                        size_t base = (((size_t)b * 16 + h) * 64 + n) * 32 + dim;
                        *(uint32_t*)(g_vh + base) =
                            pack2(__float2half_rn(acc[mi][ni][rh * 2]),
                                  __float2half_rn(acc[mi][ni][rh * 2 + 1]));
                    }
                }
            }
        }
    }
}

__global__ void __launch_bounds__(128, 2)
qkv_gemm_kernel(const float* __restrict__ logit_scale) {
    gemm_core<1>(g_xh, g_xl, g_qwh, g_qwl, g_qkvbias, nullptr, QKV_N, C_DIM, 8,
                 logit_scale);
}

__global__ void __launch_bounds__(128, 2)
proj_gemm_kernel(const float* __restrict__ proj_b, float* __restrict__ out) {
    gemm_core<0>(g_aoh, g_aoh, g_pwh, g_pwh, proj_b, out, C_DIM, C_DIM, 0, nullptr);
}

// ---------------------------------------------------------------------------
// Kernel 3: attention per (window, head). Operands pre-normalized/pre-split
// by the QKV epilogue; loaded via cp.async. QK^T 3-term, PV 1-term.
// ---------------------------------------------------------------------------
#define ATT_QH  0
#define ATT_QL  5120
#define ATT_KTH 10240
#define ATT_KTL 14848
#define ATT_VH  19456
#define ATT_SS  24576
#define ATT_TOT (24576 + 64 * 66 * 4)   // 41472 B
#define ATT_PH  0                        // P hi overlays dead Q region

__global__ void __launch_bounds__(256, 2)
attn_kernel(const float* __restrict__ mask) {
    const int bh = blockIdx.x;           // b*16 + h
    const int b  = bh >> 4;
    const int h  = bh & 15;
    const int tid  = threadIdx.x;
    const int lane = tid & 31;
    const int w    = tid >> 5;

    __shared__ __align__(16) char sm[ATT_TOT];
    __half* sPh = (__half*)(sm + ATT_PH);
    float* sS = (float*)(sm + ATT_SS);
    const uint32_t smb = (uint32_t)__cvta_generic_to_shared(sm);

    // ---- Phase 1: async-load pre-split operands ----
    {
        const __half* qh  = g_qh  + (size_t)bh * 2048;   // [64][32]
        const __half* ql  = g_ql  + (size_t)bh * 2048;
        const __half* kth = g_kth + (size_t)bh * 2048;   // [32][64]
        const __half* ktl = g_ktl + (size_t)bh * 2048;
        const __half* vh  = g_vh  + (size_t)bh * 2048;
        {
            int row = tid >> 2, ch = (tid & 3) * 8;      // [64][32] tensors
            uint32_t ds = (uint32_t)(row * 40 + ch) * 2;
            cp16(smb + ATT_QH + ds, qh + row * 32 + ch);
            cp16(smb + ATT_QL + ds, ql + row * 32 + ch);
            cp16(smb + ATT_VH + ds, vh + row * 32 + ch);
        }
        {
            int row = tid >> 3, ch = (tid & 7) * 8;      // [32][64] tensors
            uint32_t ds = (uint32_t)(row * 72 + ch) * 2;
            cp16(smb + ATT_KTH + ds, kth + row * 64 + ch);
            cp16(smb + ATT_KTL + ds, ktl + row * 64 + ch);
        }
        cp_commit();
        cp_wait0();
        __syncthreads();
    }

    // ---- Phase 2: S = Qn @ Kn^T (3-term) ----
    {
        const int m0  = (w & 3) * 16;
        const int n0  = (w >> 2) * 32;
        const int l15 = lane & 15;
        const int lhi8 = (lane >> 4) * 8;
        float acc[4][4];
        #pragma unroll
        for (int ni = 0; ni < 4; ni++)
            #pragma unroll
            for (int r = 0; r < 4; r++) acc[ni][r] = 0.f;

        #pragma unroll
        for (int ks = 0; ks < 32; ks += 16) {
            uint32_t ah[4], al[4];
            uint32_t dsA = (uint32_t)(ATT_QH) + (uint32_t)((m0 + l15) * 40 + ks + lhi8) * 2;
            ldsm_x4(ah, smb + dsA);
            ldsm_x4(al, smb + dsA + (ATT_QL - ATT_QH));
            #pragma unroll
            for (int ni = 0; ni < 4; ni++) {
                uint32_t bhf[2], blf[2];
                uint32_t dsB = (uint32_t)(ATT_KTH) + (uint32_t)((ks + l15) * 72 + n0 + ni * 8) * 2;
                ldsm_x2t(bhf, smb + dsB);
                ldsm_x2t(blf, smb + dsB + (ATT_KTL - ATT_KTH));
                mma_f16(acc[ni], ah, bhf);
                mma_f16(acc[ni], ah, blf);
                mma_f16(acc[ni], al, bhf);
            }
        }
        const int g  = lane >> 2;
        const int t2 = (lane & 3) * 2;
        #pragma unroll
        for (int ni = 0; ni < 4; ni++) {
            int c = n0 + ni * 8 + t2;
            *(float2*)&sS[(m0 + g) * 66 + c]     = make_float2(acc[ni][0], acc[ni][1]);
            *(float2*)&sS[(m0 + 8 + g) * 66 + c] = make_float2(acc[ni][2], acc[ni][3]);
        }
    }
    __syncthreads();

    // ---- Phase 3: softmax (uniform); P hi-only fp16 overlaying Q ----
    {
        const int r  = tid >> 2;
        const int c0 = (tid & 3) * 16;
        const int rr = (r < N_TOK) ? r : 0;
        const int ww = b & (NWMASK - 1);
        const float* pbr = g_pb + h * NN + rr * N_TOK;
        const float* mr  = mask + (size_t)ww * NN + rr * N_TOK;
        float vals[16];
        float mx = -1e30f;
        #pragma unroll
        for (int i = 0; i < 16; i++) {
            int m = c0 + i;
            float v = -1e30f;
            if (m < N_TOK) v = sS[r * 66 + m] + pbr[m] + mr[m];
            vals[i] = v;
            mx = fmaxf(mx, v);
        }
        mx = fmaxf(mx, __shfl_xor_sync(0xffffffff, mx, 1));
        mx = fmaxf(mx, __shfl_xor_sync(0xffffffff, mx, 2));
        float sum = 0.f;
        #pragma unroll
        for (int i = 0; i < 16; i++) {
            float e = (c0 + i < N_TOK) ? __expf(vals[i] - mx) : 0.f;
            vals[i] = e;
            sum += e;
        }
        sum += __shfl_xor_sync(0xffffffff, sum, 1);
        sum += __shfl_xor_sync(0xffffffff, sum, 2);
        float inv = 1.f / sum;
        #pragma unroll
        for (int i = 0; i < 16; i += 2) {
            *(uint32_t*)&sPh[r * 72 + c0 + i] =
                pack2(__float2half_rn(vals[i] * inv), __float2half_rn(vals[i + 1] * inv));
        }
    }
    __syncthreads();

    // ---- Phase 4: O = P @ V (1-term); hi-only output ----
    {
        const int m0  = (w & 3) * 16;
        const int n0  = (w >> 2) * 16;
        const int l15 = lane & 15;
        const int lhi8 = (lane >> 4) * 8;
        float acc[2][4];
        #pragma unroll
        for (int ni = 0; ni < 2; ni++)
            #pragma unroll
            for (int r = 0; r < 4; r++) acc[ni][r] = 0.f;

        #pragma unroll
        for (int ks = 0; ks < 64; ks += 16) {
            uint32_t ah[4];
            uint32_t dsA = (uint32_t)(ATT_PH) + (uint32_t)((m0 + l15) * 72 + ks + lhi8) * 2;
            ldsm_x4(ah, smb + dsA);
            #pragma unroll
            for (int ni = 0; ni < 2; ni++) {
                uint32_t bhf[2];
                uint32_t dsB = (uint32_t)(ATT_VH) + (uint32_t)((ks + l15) * 40 + n0 + ni * 8) * 2;
                ldsm_x2t(bhf, smb + dsB);
                mma_f16(acc[ni], ah, bhf);
            }
        }
        const int g  = lane >> 2;
        const int t2 = (lane & 3) * 2;
        #pragma unroll
        for (int ni = 0; ni < 2; ni++) {
            int col  = h * HD + n0 + ni * 8 + t2;
            int row0 = m0 + g, row1 = m0 + 8 + g;
            if (row0 < N_TOK) {
                size_t o = ((size_t)b * N_TOK + row0) * C_DIM + col;
                *(uint32_t*)(g_aoh + o) =
                    pack2(__float2half_rn(acc[ni][0]), __float2half_rn(acc[ni][1]));
            }
            if (row1 < N_TOK) {
                size_t o = ((size_t)b * N_TOK + row1) * C_DIM + col;
                *(uint32_t*)(g_aoh + o) =
                    pack2(__float2half_rn(acc[ni][2]), __float2half_rn(acc[ni][3]));
            }
        }
    }
}

// ---------------------------------------------------------------------------
// Launch
// ---------------------------------------------------------------------------
extern "C" void kernel_launch(void* const* d_in, const int* in_sizes, int n_in,
                              void* d_out, int out_size) {
    const float* x           = (const float*)d_in[0];
    const float* mask        = (const float*)d_in[1];
    const float* qkv_w       = (const float*)d_in[2];
    const float* q_bias      = (const float*)d_in[3];
    const float* v_bias      = (const float*)d_in[4];
    const float* logit_scale = (const float*)d_in[5];
    const float* rpe_w1      = (const float*)d_in[6];
    const float* rpe_b1      = (const float*)d_in[7];
    const float* rpe_w2      = (const float*)d_in[8];
    const float* proj_w      = (const float*)d_in[9];
    const float* proj_b      = (const float*)d_in[10];
    float* out = (float*)d_out;

    cudaFuncSetAttribute(qkv_gemm_kernel,
                         cudaFuncAttributeMaxDynamicSharedMemorySize, SMEM_BYTES);
    cudaFuncSetAttribute(proj_gemm_kernel,
                         cudaFuncAttributeMaxDynamicSharedMemorySize, SMEM_BYTES);

    __half *xh, *xl, *qwh, *qwl, *pwh;
    cudaGetSymbolAddress((void**)&xh,  g_xh);
    cudaGetSymbolAddress((void**)&xl,  g_xl);
    cudaGetSymbolAddress((void**)&qwh, g_qwh);
    cudaGetSymbolAddress((void**)&qwl, g_qwl);
    cudaGetSymbolAddress((void**)&pwh, g_pwh);

    setup_kernel<<<1, 256>>>(rpe_w1, rpe_b1, rpe_w2, q_bias, v_bias);

    {
        int n4 = M_ROWS * C_DIM / 4;
        split_kernel<<<(n4 + 255) / 256, 256>>>(x, xh, xl, n4);
    }
    {
        int n4 = C_DIM * QKV_N / 4;
        split_kernel<<<(n4 + 255) / 256, 256>>>(qkv_w, qwh, qwl, n4);
    }
    {
        int n4 = C_DIM * C_DIM / 4;
        split_hi_kernel<<<(n4 + 255) / 256, 256>>>(proj_w, pwh, n4);
    }

    // QKV GEMM with fused normalize/split epilogue
    qkv_gemm_kernel<<<dim3(QKV_N / 128, M_ROWS / 128), 128, SMEM_BYTES>>>(logit_scale);

    attn_kernel<<<BWIN * N_HEADS, 256>>>(mask);

    // proj: [100352,512] @ [512,512] -> d_out
    proj_gemm_kernel<<<dim3(C_DIM / 128, M_ROWS / 128), 128, SMEM_BYTES>>>(proj_b, out);
}